// round 14
// baseline (speedup 1.0000x reference)
#include <cuda_runtime.h>
#include <stdint.h>

#define HH 512
#define WW 512
#define NB 4

typedef unsigned long long ull;

// Packed border tensor: 16 channels x 2 bits per pixel (values in {0,1,2}).
__device__ uint32_t g_border[NB * HH * WW];
// Per-(batch, 32x16 tile) OR of all border words: 32 y-tiles x 16 x-tiles.
__device__ uint32_t g_tilemask[NB * 16 * 32];

__device__ __forceinline__ ull ffma2(ull a, ull b, ull c) {
    ull d;
    asm("fma.rn.f32x2 %0, %1, %2, %3;" : "=l"(d) : "l"(a), "l"(b), "l"(c));
    return d;
}
__device__ __forceinline__ ull pack2(float x, float y) {
    ull d;
    asm("mov.b64 %0, {%1, %2};" : "=l"(d) : "f"(x), "f"(y));
    return d;
}
__device__ __forceinline__ float2 unpack2(ull v) {
    float2 r;
    asm("mov.b64 {%0, %1}, %2;" : "=f"(r.x), "=f"(r.y) : "l"(v));
    return r;
}

// Spike/WTA epilogue for one pixel whose V-gate is known true.
// Identical arithmetic/order to all prior passing rounds.
__device__ __forceinline__ uint32_t epilogue_word(const ull* acc) {
    int b13[4], b24[4];
    #pragma unroll
    for (int o = 0; o < 4; ++o) {
        float2 e = unpack2(acc[2*o]);      // .x=pos even, .y=neg even
        float2 d = unpack2(acc[2*o+1]);    // .x=pos odd,  .y=neg odd
        bool pe = e.x >= 1.0f;
        bool ne = e.y >= 1.0f;
        bool po = d.x >= 1.0f;
        bool no = d.y >= 1.0f;
        int s1 = (pe && !no) ? 1 : 0;
        int s2 = (ne && !po) ? 1 : 0;
        int s3 = (po && !ne) ? 1 : 0;
        int s4 = (no && !pe) ? 1 : 0;
        b13[o] = s1 + s2;
        b24[o] = s3 + s4;
    }
    int tmax = 0;
    #pragma unroll
    for (int o = 0; o < 4; ++o) {
        int d = b13[o] - b24[o];
        int tp = d < 0 ? -d : d;
        if (tp > tmax) tmax = tp;
    }
    uint32_t word = 0;
    #pragma unroll
    for (int o = 0; o < 4; ++o) {
        int d = b13[o] - b24[o];
        int tp = d < 0 ? -d : d;
        uint32_t nib = 0;
        if (tp == tmax) {
            if (d >= 1)
                nib = (uint32_t)b13[o] | ((uint32_t)b24[o] << 2);
            else if (d <= -1)
                nib = ((uint32_t)b24[o] << 4) | ((uint32_t)b13[o] << 6);
        }
        word |= nib << (8 * o);
    }
    return word;
}

// ---------------------------------------------------------------------------
// Stage 1: 11x11 conv (1->8 ch) + spike/WTA, VM-GATED COMPACTION v2.
// Phase 1 ballots V-true pixels (V = in0+in1 >= 1; ~50%) into a shared list.
// Phase 2 processes TWO list pixels per thread per iteration: per tap,
// 4 weight LDS.128 + 2 data LDS.64 feed 16 FFMA2. Block (32,4), tile 32x16.
// R14: occupancy bound relaxed 6 -> 4 blocks/SM so the 32 accumulator regs
// + in-flight operands fit without spilling (84-reg cap was forcing LDL/STL
// onto the critical path -> 4.4 cyc/FFMA2 instead of 3.0).
// Also zeroes d_out and publishes the tile mask.
// ---------------------------------------------------------------------------
__global__ __launch_bounds__(128, 4)
void stage1_kernel(const float* __restrict__ inp, const float* __restrict__ Wb,
                   float* __restrict__ out)
{
    __shared__ ull s01[26][44];                  // (in0,in1) packed (9.2 KB)
    __shared__ __align__(16) ull dsh[121 * 8];   // dup weights [t][f] (7.7 KB)
    __shared__ uint16_t list[512];               // compacted V-true pixels
    __shared__ int cnt;

    const int b  = blockIdx.z;
    const int x0 = blockIdx.x * 32;
    const int y0 = blockIdx.y * 16;
    const int tx = threadIdx.x;      // 0..31 (= lane)
    const int ty = threadIdx.y;      // 0..3  (= warp)
    const int tid = ty * 32 + tx;

    if (tid == 0) cnt = 0;

    for (int i = tid; i < 968; i += 128) {
        int t = i >> 3, f = i & 7;
        float w = Wb[f * 121 + t];
        dsh[i] = pack2(w, w);
    }

    const float* __restrict__ in0 = inp + ((size_t)b * 2 + 0) * HH * WW;
    const float* __restrict__ in1 = inp + ((size_t)b * 2 + 1) * HH * WW;

    for (int ry = ty; ry < 26; ry += 4) {
        int gy = y0 - 5 + ry;
        for (int rx = tx; rx < 42; rx += 32) {
            int gx = x0 - 5 + rx;
            bool ok = ((unsigned)gy < HH) && ((unsigned)gx < WW);
            float v0 = ok ? in0[gy * WW + gx] : 0.0f;
            float v1 = ok ? in1[gy * WW + gx] : 0.0f;
            s01[ry][rx] = pack2(v0, v1);
        }
    }
    __syncthreads();

    // ---- Phase 1: V test, default stores, warp-aggregated compaction ----
    #pragma unroll
    for (int k = 0; k < 4; ++k) {
        const int yy = ty + k * 4;
        float2 c = unpack2(s01[yy + 5][tx + 5]);
        bool V = (c.x + c.y) >= 1.0f;

        const size_t pix = ((size_t)b * HH + (y0 + yy)) * WW + (x0 + tx);
        out[pix] = 0.0f;
        if (!V) g_border[pix] = 0u;      // V-true pixels stored in phase 2

        unsigned m = __ballot_sync(0xFFFFFFFFu, V);
        int rank = __popc(m & ((1u << tx) - 1u));
        int base = 0;
        if (tx == 0) base = atomicAdd(&cnt, __popc(m));
        base = __shfl_sync(0xFFFFFFFFu, base, 0);
        if (V) list[base + rank] = (uint16_t)((yy << 5) | tx);
    }
    __syncthreads();
    const int C = cnt;

    // ---- Phase 2: conv + spike/WTA, two compacted pixels per thread ----
    uint32_t myor = 0;
    for (int i = tid; i < C; i += 256) {
        const int j = i + 128;
        const bool hasj = (j < C);
        const int pv0 = list[i];
        const int pv1 = hasj ? list[j] : pv0;   // dup: computed, not stored
        const int py0 = pv0 >> 5, px0 = pv0 & 31;
        const int py1 = pv1 >> 5, px1 = pv1 & 31;

        ull a0[8], a1[8];
        #pragma unroll
        for (int f = 0; f < 8; ++f) { a0[f] = 0ull; a1[f] = 0ull; }

        #pragma unroll 1
        for (int dy = 0; dy < 11; ++dy) {
            #pragma unroll
            for (int dx = 0; dx < 11; ++dx) {
                ull xA = s01[py0 + dy][px0 + dx];
                ull xB = s01[py1 + dy][px1 + dx];
                const ulonglong2* wp =
                    (const ulonglong2*)&dsh[(dy * 11 + dx) * 8];
                #pragma unroll
                for (int fp = 0; fp < 4; ++fp) {
                    ulonglong2 w2 = wp[fp];
                    a0[2*fp]   = ffma2(w2.x, xA, a0[2*fp]);
                    a1[2*fp]   = ffma2(w2.x, xB, a1[2*fp]);
                    a0[2*fp+1] = ffma2(w2.y, xA, a0[2*fp+1]);
                    a1[2*fp+1] = ffma2(w2.y, xB, a1[2*fp+1]);
                }
            }
        }

        uint32_t w0 = epilogue_word(a0);
        g_border[((size_t)b * HH + (y0 + py0)) * WW + (x0 + px0)] = w0;
        myor |= w0;
        if (hasj) {
            uint32_t w1 = epilogue_word(a1);
            g_border[((size_t)b * HH + (y0 + py1)) * WW + (x0 + px1)] = w1;
            myor |= w1;
        }
    }

    // Publish this 32x16 tile's OR so stage2 can skip before loading anything.
    uint32_t tileor = (uint32_t)__syncthreads_or((int)myor);
    if (tid == 0)
        g_tilemask[b * 512 + blockIdx.y * 16 + blockIdx.x] = tileor;
}

// ---------------------------------------------------------------------------
// Stage 2: depthwise 23x23 conv + spike combination. ONE (tile, group) per
// block. EARLY SKIP: probe <=21 tile-mask words covering the halo; if this
// group's nibble is zero there, exit before loading weights or halo.
// Block (32,4), tile 32x64, 16 output rows/thread, rolling window +
// depth-1 weight prefetch. Results combine via predicated atomicAdd.
// ---------------------------------------------------------------------------
__global__ __launch_bounds__(128)
void stage2_kernel(const float* __restrict__ Wg, float* __restrict__ out)
{
    __shared__ ull sh[86][55];    // decoded (chanA, chanB) pairs (37.8 KB)
    __shared__ ull wsh[529];      // duplicated weights (4.2 KB)

    const int zz  = blockIdx.z;          // 0..31 = b*8 + grp
    const int b   = zz >> 3;
    const int grp = zz & 7;
    const int x0 = blockIdx.x * 32;
    const int y0 = blockIdx.y * 64;
    const int tx = threadIdx.x;   // 0..31
    const int ty = threadIdx.y;   // 0..3
    const int tid = ty * 32 + tx;
    const int yb = ty * 16;
    const int shift = grp * 4;

    // ---- mask probe: OR the <=21 tile-masks (32x16 each) over the halo ----
    {
        const int txl = (x0 >= 11 ? x0 - 11 : 0) >> 5;
        const int txh = ((x0 + 42 < WW ? x0 + 42 : WW - 1)) >> 5;
        const int tyl = (y0 >= 11 ? y0 - 11 : 0) >> 4;
        const int tyh = ((y0 + 74 < HH ? y0 + 74 : HH - 1)) >> 4;
        const int nx = txh - txl + 1;            // <=3
        const int nt = nx * (tyh - tyl + 1);     // <=21
        uint32_t m = 0;
        if (tid < nt) {
            int tyi = tyl + tid / nx;
            int txi = txl + tid % nx;
            m = g_tilemask[b * 512 + tyi * 16 + txi];
        }
        int any = __syncthreads_or((int)((m >> shift) & 0xFu));
        if (!any) return;   // group empty over whole halo -> output untouched
    }

    const uint32_t* __restrict__ bor = g_border + (size_t)b * HH * WW;

    for (int i = tid; i < 529; i += 128) {
        float w = Wg[grp * 2 * 529 + i];
        wsh[i] = pack2(w, w);
    }

    for (int ry = ty; ry < 86; ry += 4) {
        int gy = y0 - 11 + ry;
        for (int rx = tx; rx < 54; rx += 32) {
            int gx = x0 - 11 + rx;
            uint32_t v = 0;
            if (((unsigned)gy < HH) && ((unsigned)gx < WW)) v = bor[gy * WW + gx];
            sh[ry][rx] = pack2((float)((v >> shift) & 3u),
                               (float)((v >> (shift + 2)) & 3u));
        }
    }
    __syncthreads();

    ull a[16];
    #pragma unroll
    for (int o = 0; o < 16; ++o) a[o] = 0ull;

    #pragma unroll 1
    for (int dx = 0; dx < 23; ++dx) {
        const int c = tx + dx;

        ull r[16];
        #pragma unroll
        for (int o = 0; o < 16; ++o) r[o] = sh[yb + o][c];

        ull w0 = wsh[dx];   // weight for dy=0
        #pragma unroll
        for (int dy = 0; dy < 23; ++dy) {
            ull wn = (dy < 22) ? wsh[(dy + 1) * 23 + dx] : 0ull;
            #pragma unroll
            for (int o = 0; o < 16; ++o) a[o] = ffma2(w0, r[o], a[o]);
            if (dy < 22) {
                #pragma unroll
                for (int o = 0; o < 15; ++o) r[o] = r[o + 1];
                r[15] = sh[yb + dy + 16][c];
            }
            w0 = wn;
        }
    }

    #pragma unroll
    for (int o = 0; o < 16; ++o) {
        float2 v = unpack2(a[o]);
        if (v.x >= 1.0f && v.y < 1.0f)
            atomicAdd(&out[((size_t)b * HH + (y0 + yb + o)) * WW + x0 + tx], 1.0f);
    }
}

// ---------------------------------------------------------------------------
extern "C" void kernel_launch(void* const* d_in, const int* in_sizes, int n_in,
                              void* d_out, int out_size)
{
    const float* inp = nullptr;
    const float* Wb  = nullptr;
    const float* Wg  = nullptr;
    for (int i = 0; i < n_in; ++i) {
        if (in_sizes[i] == NB * 2 * HH * WW) inp = (const float*)d_in[i];
        else if (in_sizes[i] == 8 * 121)     Wb  = (const float*)d_in[i];
        else if (in_sizes[i] == 16 * 529)    Wg  = (const float*)d_in[i];
    }

    dim3 grid1(WW / 32, HH / 16, NB);        // 32x16 tiles
    dim3 blk1(32, 4);
    stage1_kernel<<<grid1, blk1>>>(inp, Wb, (float*)d_out);

    dim3 grid2(WW / 32, HH / 64, NB * 8);    // one (32x64 tile, group) per block
    dim3 blk2(32, 4);
    stage2_kernel<<<grid2, blk2>>>(Wg, (float*)d_out);
}

// round 15
// speedup vs baseline: 1.1234x; 1.1234x over previous
#include <cuda_runtime.h>
#include <stdint.h>

#define HH 512
#define WW 512
#define NB 4

typedef unsigned long long ull;

// Packed border tensor: 16 channels x 2 bits per pixel (values in {0,1,2}).
__device__ uint32_t g_border[NB * HH * WW];
// Per-(batch, 32x32 tile) OR of all border words: 16 x 16 tiles per batch.
__device__ uint32_t g_tilemask[NB * 16 * 16];

__device__ __forceinline__ ull ffma2(ull a, ull b, ull c) {
    ull d;
    asm("fma.rn.f32x2 %0, %1, %2, %3;" : "=l"(d) : "l"(a), "l"(b), "l"(c));
    return d;
}
__device__ __forceinline__ ull pack2(float x, float y) {
    ull d;
    asm("mov.b64 %0, {%1, %2};" : "=l"(d) : "f"(x), "f"(y));
    return d;
}
__device__ __forceinline__ float2 unpack2(ull v) {
    float2 r;
    asm("mov.b64 {%0, %1}, %2;" : "=f"(r.x), "=f"(r.y) : "l"(v));
    return r;
}

// Spike/WTA epilogue for one pixel whose V-gate is known true.
// Identical arithmetic/order to all prior passing rounds.
__device__ __forceinline__ uint32_t epilogue_word(const ull* acc) {
    int b13[4], b24[4];
    #pragma unroll
    for (int o = 0; o < 4; ++o) {
        float2 e = unpack2(acc[2*o]);      // .x=pos even, .y=neg even
        float2 d = unpack2(acc[2*o+1]);    // .x=pos odd,  .y=neg odd
        bool pe = e.x >= 1.0f;
        bool ne = e.y >= 1.0f;
        bool po = d.x >= 1.0f;
        bool no = d.y >= 1.0f;
        int s1 = (pe && !no) ? 1 : 0;
        int s2 = (ne && !po) ? 1 : 0;
        int s3 = (po && !ne) ? 1 : 0;
        int s4 = (no && !pe) ? 1 : 0;
        b13[o] = s1 + s2;
        b24[o] = s3 + s4;
    }
    int tmax = 0;
    #pragma unroll
    for (int o = 0; o < 4; ++o) {
        int d = b13[o] - b24[o];
        int tp = d < 0 ? -d : d;
        if (tp > tmax) tmax = tp;
    }
    uint32_t word = 0;
    #pragma unroll
    for (int o = 0; o < 4; ++o) {
        int d = b13[o] - b24[o];
        int tp = d < 0 ? -d : d;
        uint32_t nib = 0;
        if (tp == tmax) {
            if (d >= 1)
                nib = (uint32_t)b13[o] | ((uint32_t)b24[o] << 2);
            else if (d <= -1)
                nib = ((uint32_t)b24[o] << 4) | ((uint32_t)b13[o] << 6);
        }
        word |= nib << (8 * o);
    }
    return word;
}

// ---------------------------------------------------------------------------
// Stage 1: 11x11 conv (1->8 ch) + spike/WTA, VM-GATED COMPACTION v3.
// Tile 32x32 per block (C ~ 512+-16), block (32,4). Phase 2 processes FOUR
// list pixels per thread per pass: per tap, 4 weight LDS.128 + 4 scattered
// LDS.64 feed 32 FFMA2 -> LSU ~18 cyc < FMA 24 cyc per SM: FMA-bound again
// (R13's pair loop was LSU-bound on scattered-load conflicts).
// Typical C<=512 -> exactly one pass. Also zeroes d_out + publishes mask.
// ---------------------------------------------------------------------------
__global__ __launch_bounds__(128, 4)
void stage1_kernel(const float* __restrict__ inp, const float* __restrict__ Wb,
                   float* __restrict__ out)
{
    __shared__ ull s01[42 * 44];                 // (in0,in1) packed (14.8 KB)
    __shared__ __align__(16) ull dsh[121 * 8];   // dup weights [t][f] (7.7 KB)
    __shared__ uint16_t list[1024];              // compacted V-true pixels
    __shared__ int cnt;

    const int b  = blockIdx.z;
    const int x0 = blockIdx.x * 32;
    const int y0 = blockIdx.y * 32;
    const int tx = threadIdx.x;      // 0..31 (= lane)
    const int ty = threadIdx.y;      // 0..3  (= warp)
    const int tid = ty * 32 + tx;

    if (tid == 0) cnt = 0;

    for (int i = tid; i < 968; i += 128) {
        int t = i >> 3, f = i & 7;
        float w = Wb[f * 121 + t];
        dsh[i] = pack2(w, w);
    }

    const float* __restrict__ in0 = inp + ((size_t)b * 2 + 0) * HH * WW;
    const float* __restrict__ in1 = inp + ((size_t)b * 2 + 1) * HH * WW;

    for (int ry = ty; ry < 42; ry += 4) {
        int gy = y0 - 5 + ry;
        for (int rx = tx; rx < 42; rx += 32) {
            int gx = x0 - 5 + rx;
            bool ok = ((unsigned)gy < HH) && ((unsigned)gx < WW);
            float v0 = ok ? in0[gy * WW + gx] : 0.0f;
            float v1 = ok ? in1[gy * WW + gx] : 0.0f;
            s01[ry * 44 + rx] = pack2(v0, v1);
        }
    }
    __syncthreads();

    // ---- Phase 1: V test, default stores, warp-aggregated compaction ----
    #pragma unroll
    for (int k = 0; k < 8; ++k) {
        const int yy = ty + k * 4;
        float2 c = unpack2(s01[(yy + 5) * 44 + tx + 5]);
        bool V = (c.x + c.y) >= 1.0f;

        const size_t pix = ((size_t)b * HH + (y0 + yy)) * WW + (x0 + tx);
        out[pix] = 0.0f;
        if (!V) g_border[pix] = 0u;      // V-true pixels stored in phase 2

        unsigned m = __ballot_sync(0xFFFFFFFFu, V);
        int rank = __popc(m & ((1u << tx) - 1u));
        int base = 0;
        if (tx == 0) base = atomicAdd(&cnt, __popc(m));
        base = __shfl_sync(0xFFFFFFFFu, base, 0);
        if (V) list[base + rank] = (uint16_t)((yy << 5) | tx);
    }
    __syncthreads();
    const int C = cnt;

    // ---- Phase 2: conv + spike/WTA, FOUR compacted pixels per thread ----
    uint32_t myor = 0;
    for (int i = tid; i < C; i += 512) {
        const int i1 = i + 128, i2 = i + 256, i3 = i + 384;
        const bool h1 = (i1 < C), h2 = (i2 < C), h3 = (i3 < C);
        const int pv0 = list[i];
        const int pv1 = h1 ? list[i1] : pv0;   // dups: computed, not stored
        const int pv2 = h2 ? list[i2] : pv0;
        const int pv3 = h3 ? list[i3] : pv0;
        const int o0 = (pv0 >> 5) * 44 + (pv0 & 31);
        const int o1 = (pv1 >> 5) * 44 + (pv1 & 31);
        const int o2 = (pv2 >> 5) * 44 + (pv2 & 31);
        const int o3 = (pv3 >> 5) * 44 + (pv3 & 31);

        ull a0[8], a1[8], a2[8], a3[8];
        #pragma unroll
        for (int f = 0; f < 8; ++f) {
            a0[f] = 0ull; a1[f] = 0ull; a2[f] = 0ull; a3[f] = 0ull;
        }

        #pragma unroll 1
        for (int dy = 0; dy < 11; ++dy) {
            #pragma unroll
            for (int dx = 0; dx < 11; ++dx) {
                const int off = dy * 44 + dx;
                ull xA = s01[o0 + off];
                ull xB = s01[o1 + off];
                ull xC = s01[o2 + off];
                ull xD = s01[o3 + off];
                const ulonglong2* wp =
                    (const ulonglong2*)&dsh[(dy * 11 + dx) * 8];
                #pragma unroll
                for (int fp = 0; fp < 4; ++fp) {
                    ulonglong2 w2 = wp[fp];
                    a0[2*fp]   = ffma2(w2.x, xA, a0[2*fp]);
                    a1[2*fp]   = ffma2(w2.x, xB, a1[2*fp]);
                    a2[2*fp]   = ffma2(w2.x, xC, a2[2*fp]);
                    a3[2*fp]   = ffma2(w2.x, xD, a3[2*fp]);
                    a0[2*fp+1] = ffma2(w2.y, xA, a0[2*fp+1]);
                    a1[2*fp+1] = ffma2(w2.y, xB, a1[2*fp+1]);
                    a2[2*fp+1] = ffma2(w2.y, xC, a2[2*fp+1]);
                    a3[2*fp+1] = ffma2(w2.y, xD, a3[2*fp+1]);
                }
            }
        }

        const size_t rowbase = (size_t)b * HH * WW;
        uint32_t w0 = epilogue_word(a0);
        g_border[rowbase + (size_t)(y0 + (pv0 >> 5)) * WW + (x0 + (pv0 & 31))] = w0;
        myor |= w0;
        if (h1) {
            uint32_t w1 = epilogue_word(a1);
            g_border[rowbase + (size_t)(y0 + (pv1 >> 5)) * WW + (x0 + (pv1 & 31))] = w1;
            myor |= w1;
        }
        if (h2) {
            uint32_t w2v = epilogue_word(a2);
            g_border[rowbase + (size_t)(y0 + (pv2 >> 5)) * WW + (x0 + (pv2 & 31))] = w2v;
            myor |= w2v;
        }
        if (h3) {
            uint32_t w3 = epilogue_word(a3);
            g_border[rowbase + (size_t)(y0 + (pv3 >> 5)) * WW + (x0 + (pv3 & 31))] = w3;
            myor |= w3;
        }
    }

    // Publish this 32x32 tile's OR so stage2 can skip before loading anything.
    uint32_t tileor = (uint32_t)__syncthreads_or((int)myor);
    if (tid == 0)
        g_tilemask[b * 256 + blockIdx.y * 16 + blockIdx.x] = tileor;
}

// ---------------------------------------------------------------------------
// Stage 2: depthwise 23x23 conv + spike combination. ONE (tile, group) per
// block. EARLY SKIP: probe <=12 tile-mask words (32x32 each) over the halo;
// if this group's nibble is zero there, exit before loading anything.
// Block (32,4), tile 32x64, 16 output rows/thread, rolling window +
// depth-1 weight prefetch. Results combine via predicated atomicAdd.
// ---------------------------------------------------------------------------
__global__ __launch_bounds__(128)
void stage2_kernel(const float* __restrict__ Wg, float* __restrict__ out)
{
    __shared__ ull sh[86][55];    // decoded (chanA, chanB) pairs (37.8 KB)
    __shared__ ull wsh[529];      // duplicated weights (4.2 KB)

    const int zz  = blockIdx.z;          // 0..31 = b*8 + grp
    const int b   = zz >> 3;
    const int grp = zz & 7;
    const int x0 = blockIdx.x * 32;
    const int y0 = blockIdx.y * 64;
    const int tx = threadIdx.x;   // 0..31
    const int ty = threadIdx.y;   // 0..3
    const int tid = ty * 32 + tx;
    const int yb = ty * 16;
    const int shift = grp * 4;

    // ---- mask probe: OR the <=12 tile-masks (32x32 each) over the halo ----
    {
        const int txl = (x0 >= 11 ? x0 - 11 : 0) >> 5;
        const int txh = ((x0 + 42 < WW ? x0 + 42 : WW - 1)) >> 5;
        const int tyl = (y0 >= 11 ? y0 - 11 : 0) >> 5;
        const int tyh = ((y0 + 74 < HH ? y0 + 74 : HH - 1)) >> 5;
        const int nx = txh - txl + 1;            // <=3
        const int nt = nx * (tyh - tyl + 1);     // <=12
        uint32_t m = 0;
        if (tid < nt) {
            int tyi = tyl + tid / nx;
            int txi = txl + tid % nx;
            m = g_tilemask[b * 256 + tyi * 16 + txi];
        }
        int any = __syncthreads_or((int)((m >> shift) & 0xFu));
        if (!any) return;   // group empty over whole halo -> output untouched
    }

    const uint32_t* __restrict__ bor = g_border + (size_t)b * HH * WW;

    for (int i = tid; i < 529; i += 128) {
        float w = Wg[grp * 2 * 529 + i];
        wsh[i] = pack2(w, w);
    }

    for (int ry = ty; ry < 86; ry += 4) {
        int gy = y0 - 11 + ry;
        for (int rx = tx; rx < 54; rx += 32) {
            int gx = x0 - 11 + rx;
            uint32_t v = 0;
            if (((unsigned)gy < HH) && ((unsigned)gx < WW)) v = bor[gy * WW + gx];
            sh[ry][rx] = pack2((float)((v >> shift) & 3u),
                               (float)((v >> (shift + 2)) & 3u));
        }
    }
    __syncthreads();

    ull a[16];
    #pragma unroll
    for (int o = 0; o < 16; ++o) a[o] = 0ull;

    #pragma unroll 1
    for (int dx = 0; dx < 23; ++dx) {
        const int c = tx + dx;

        ull r[16];
        #pragma unroll
        for (int o = 0; o < 16; ++o) r[o] = sh[yb + o][c];

        ull w0 = wsh[dx];   // weight for dy=0
        #pragma unroll
        for (int dy = 0; dy < 23; ++dy) {
            ull wn = (dy < 22) ? wsh[(dy + 1) * 23 + dx] : 0ull;
            #pragma unroll
            for (int o = 0; o < 16; ++o) a[o] = ffma2(w0, r[o], a[o]);
            if (dy < 22) {
                #pragma unroll
                for (int o = 0; o < 15; ++o) r[o] = r[o + 1];
                r[15] = sh[yb + dy + 16][c];
            }
            w0 = wn;
        }
    }

    #pragma unroll
    for (int o = 0; o < 16; ++o) {
        float2 v = unpack2(a[o]);
        if (v.x >= 1.0f && v.y < 1.0f)
            atomicAdd(&out[((size_t)b * HH + (y0 + yb + o)) * WW + x0 + tx], 1.0f);
    }
}

// ---------------------------------------------------------------------------
extern "C" void kernel_launch(void* const* d_in, const int* in_sizes, int n_in,
                              void* d_out, int out_size)
{
    const float* inp = nullptr;
    const float* Wb  = nullptr;
    const float* Wg  = nullptr;
    for (int i = 0; i < n_in; ++i) {
        if (in_sizes[i] == NB * 2 * HH * WW) inp = (const float*)d_in[i];
        else if (in_sizes[i] == 8 * 121)     Wb  = (const float*)d_in[i];
        else if (in_sizes[i] == 16 * 529)    Wg  = (const float*)d_in[i];
    }

    dim3 grid1(WW / 32, HH / 32, NB);        // 32x32 tiles
    dim3 blk1(32, 4);
    stage1_kernel<<<grid1, blk1>>>(inp, Wb, (float*)d_out);

    dim3 grid2(WW / 32, HH / 64, NB * 8);    // one (32x64 tile, group) per block
    dim3 blk2(32, 4);
    stage2_kernel<<<grid2, blk2>>>(Wg, (float*)d_out);
}

// round 16
// speedup vs baseline: 1.2554x; 1.1175x over previous
#include <cuda_runtime.h>
#include <stdint.h>

#define HH 512
#define WW 512
#define NB 4

typedef unsigned long long ull;

// Packed border tensor: 16 channels x 2 bits per pixel (values in {0,1,2}).
__device__ uint32_t g_border[NB * HH * WW];
// Per-(batch, 32x32 tile) OR of all border words: 16 x 16 tiles per batch.
__device__ uint32_t g_tilemask[NB * 16 * 16];

__device__ __forceinline__ ull ffma2(ull a, ull b, ull c) {
    ull d;
    asm("fma.rn.f32x2 %0, %1, %2, %3;" : "=l"(d) : "l"(a), "l"(b), "l"(c));
    return d;
}
__device__ __forceinline__ ull pack2(float x, float y) {
    ull d;
    asm("mov.b64 %0, {%1, %2};" : "=l"(d) : "f"(x), "f"(y));
    return d;
}
__device__ __forceinline__ float2 unpack2(ull v) {
    float2 r;
    asm("mov.b64 {%0, %1}, %2;" : "=f"(r.x), "=f"(r.y) : "l"(v));
    return r;
}

// Spike/WTA epilogue for one pixel whose V-gate is known true.
// Identical arithmetic/order to all prior passing rounds.
__device__ __forceinline__ uint32_t epilogue_word(const ull* acc) {
    int b13[4], b24[4];
    #pragma unroll
    for (int o = 0; o < 4; ++o) {
        float2 e = unpack2(acc[2*o]);      // .x=pos even, .y=neg even
        float2 d = unpack2(acc[2*o+1]);    // .x=pos odd,  .y=neg odd
        bool pe = e.x >= 1.0f;
        bool ne = e.y >= 1.0f;
        bool po = d.x >= 1.0f;
        bool no = d.y >= 1.0f;
        int s1 = (pe && !no) ? 1 : 0;
        int s2 = (ne && !po) ? 1 : 0;
        int s3 = (po && !ne) ? 1 : 0;
        int s4 = (no && !pe) ? 1 : 0;
        b13[o] = s1 + s2;
        b24[o] = s3 + s4;
    }
    int tmax = 0;
    #pragma unroll
    for (int o = 0; o < 4; ++o) {
        int d = b13[o] - b24[o];
        int tp = d < 0 ? -d : d;
        if (tp > tmax) tmax = tp;
    }
    uint32_t word = 0;
    #pragma unroll
    for (int o = 0; o < 4; ++o) {
        int d = b13[o] - b24[o];
        int tp = d < 0 ? -d : d;
        uint32_t nib = 0;
        if (tp == tmax) {
            if (d >= 1)
                nib = (uint32_t)b13[o] | ((uint32_t)b24[o] << 2);
            else if (d <= -1)
                nib = ((uint32_t)b24[o] << 4) | ((uint32_t)b13[o] << 6);
        }
        word |= nib << (8 * o);
    }
    return word;
}

// ---------------------------------------------------------------------------
// Stage 1: 11x11 conv (1->8 ch) + spike/WTA, VM-GATED COMPACTION v4.
// Tile 32x32 per block (C ~ 512+-16), block (32,4).
// Phase 2a: ONE unrolled pass over the first min(C,512) pixels, 4 per thread
// (per tap: 4 weight LDS.128 + 4 near-coherent LDS.64 feed 32 FFMA2).
// Phase 2b: cheap 1-pixel-per-thread remainder loop for pixels 512..C —
// replaces R15's full-cost straggler pass (~11.6K cyc) with ~3.1K cyc.
// Also zeroes d_out and publishes the tile OR-mask.
// ---------------------------------------------------------------------------
__global__ __launch_bounds__(128, 4)
void stage1_kernel(const float* __restrict__ inp, const float* __restrict__ Wb,
                   float* __restrict__ out)
{
    __shared__ ull s01[42 * 44];                 // (in0,in1) packed (14.8 KB)
    __shared__ __align__(16) ull dsh[121 * 8];   // dup weights [t][f] (7.7 KB)
    __shared__ uint16_t list[1024];              // compacted V-true pixels
    __shared__ int cnt;

    const int b  = blockIdx.z;
    const int x0 = blockIdx.x * 32;
    const int y0 = blockIdx.y * 32;
    const int tx = threadIdx.x;      // 0..31 (= lane)
    const int ty = threadIdx.y;      // 0..3  (= warp)
    const int tid = ty * 32 + tx;

    if (tid == 0) cnt = 0;

    for (int i = tid; i < 968; i += 128) {
        int t = i >> 3, f = i & 7;
        float w = Wb[f * 121 + t];
        dsh[i] = pack2(w, w);
    }

    const float* __restrict__ in0 = inp + ((size_t)b * 2 + 0) * HH * WW;
    const float* __restrict__ in1 = inp + ((size_t)b * 2 + 1) * HH * WW;

    for (int ry = ty; ry < 42; ry += 4) {
        int gy = y0 - 5 + ry;
        for (int rx = tx; rx < 42; rx += 32) {
            int gx = x0 - 5 + rx;
            bool ok = ((unsigned)gy < HH) && ((unsigned)gx < WW);
            float v0 = ok ? in0[gy * WW + gx] : 0.0f;
            float v1 = ok ? in1[gy * WW + gx] : 0.0f;
            s01[ry * 44 + rx] = pack2(v0, v1);
        }
    }
    __syncthreads();

    // ---- Phase 1: V test, default stores, warp-aggregated compaction ----
    #pragma unroll
    for (int k = 0; k < 8; ++k) {
        const int yy = ty + k * 4;
        float2 c = unpack2(s01[(yy + 5) * 44 + tx + 5]);
        bool V = (c.x + c.y) >= 1.0f;

        const size_t pix = ((size_t)b * HH + (y0 + yy)) * WW + (x0 + tx);
        out[pix] = 0.0f;
        if (!V) g_border[pix] = 0u;      // V-true pixels stored in phase 2

        unsigned m = __ballot_sync(0xFFFFFFFFu, V);
        int rank = __popc(m & ((1u << tx) - 1u));
        int base = 0;
        if (tx == 0) base = atomicAdd(&cnt, __popc(m));
        base = __shfl_sync(0xFFFFFFFFu, base, 0);
        if (V) list[base + rank] = (uint16_t)((yy << 5) | tx);
    }
    __syncthreads();
    const int C = cnt;
    const size_t rowbase = (size_t)b * HH * WW;
    uint32_t myor = 0;

    // ---- Phase 2a: single unrolled pass, 4 pixels/thread, first 512 ----
    {
        const int i0 = tid, i1 = tid + 128, i2 = tid + 256, i3 = tid + 384;
        const bool h0 = (i0 < C), h1 = (i1 < C), h2 = (i2 < C), h3 = (i3 < C);
        const int pv0 = h0 ? list[i0] : 0;   // dummies compute, never store
        const int pv1 = h1 ? list[i1] : pv0;
        const int pv2 = h2 ? list[i2] : pv0;
        const int pv3 = h3 ? list[i3] : pv0;
        const int o0 = (pv0 >> 5) * 44 + (pv0 & 31);
        const int o1 = (pv1 >> 5) * 44 + (pv1 & 31);
        const int o2 = (pv2 >> 5) * 44 + (pv2 & 31);
        const int o3 = (pv3 >> 5) * 44 + (pv3 & 31);

        ull a0[8], a1[8], a2[8], a3[8];
        #pragma unroll
        for (int f = 0; f < 8; ++f) {
            a0[f] = 0ull; a1[f] = 0ull; a2[f] = 0ull; a3[f] = 0ull;
        }

        #pragma unroll 1
        for (int dy = 0; dy < 11; ++dy) {
            #pragma unroll
            for (int dx = 0; dx < 11; ++dx) {
                const int off = dy * 44 + dx;
                ull xA = s01[o0 + off];
                ull xB = s01[o1 + off];
                ull xC = s01[o2 + off];
                ull xD = s01[o3 + off];
                const ulonglong2* wp =
                    (const ulonglong2*)&dsh[(dy * 11 + dx) * 8];
                #pragma unroll
                for (int fp = 0; fp < 4; ++fp) {
                    ulonglong2 w2 = wp[fp];
                    a0[2*fp]   = ffma2(w2.x, xA, a0[2*fp]);
                    a1[2*fp]   = ffma2(w2.x, xB, a1[2*fp]);
                    a2[2*fp]   = ffma2(w2.x, xC, a2[2*fp]);
                    a3[2*fp]   = ffma2(w2.x, xD, a3[2*fp]);
                    a0[2*fp+1] = ffma2(w2.y, xA, a0[2*fp+1]);
                    a1[2*fp+1] = ffma2(w2.y, xB, a1[2*fp+1]);
                    a2[2*fp+1] = ffma2(w2.y, xC, a2[2*fp+1]);
                    a3[2*fp+1] = ffma2(w2.y, xD, a3[2*fp+1]);
                }
            }
        }

        if (h0) {
            uint32_t w0 = epilogue_word(a0);
            g_border[rowbase + (size_t)(y0 + (pv0 >> 5)) * WW + (x0 + (pv0 & 31))] = w0;
            myor |= w0;
        }
        if (h1) {
            uint32_t w1 = epilogue_word(a1);
            g_border[rowbase + (size_t)(y0 + (pv1 >> 5)) * WW + (x0 + (pv1 & 31))] = w1;
            myor |= w1;
        }
        if (h2) {
            uint32_t w2v = epilogue_word(a2);
            g_border[rowbase + (size_t)(y0 + (pv2 >> 5)) * WW + (x0 + (pv2 & 31))] = w2v;
            myor |= w2v;
        }
        if (h3) {
            uint32_t w3 = epilogue_word(a3);
            g_border[rowbase + (size_t)(y0 + (pv3 >> 5)) * WW + (x0 + (pv3 & 31))] = w3;
            myor |= w3;
        }
    }

    // ---- Phase 2b: cheap 1-pixel remainder for pixels 512..C ----
    for (int i = 512 + tid; i < C; i += 128) {
        const int pv = list[i];
        const int ob = (pv >> 5) * 44 + (pv & 31);

        ull a[8];
        #pragma unroll
        for (int f = 0; f < 8; ++f) a[f] = 0ull;

        #pragma unroll 1
        for (int dy = 0; dy < 11; ++dy) {
            #pragma unroll
            for (int dx = 0; dx < 11; ++dx) {
                ull x = s01[ob + dy * 44 + dx];
                const ulonglong2* wp =
                    (const ulonglong2*)&dsh[(dy * 11 + dx) * 8];
                #pragma unroll
                for (int fp = 0; fp < 4; ++fp) {
                    ulonglong2 w2 = wp[fp];
                    a[2*fp]   = ffma2(w2.x, x, a[2*fp]);
                    a[2*fp+1] = ffma2(w2.y, x, a[2*fp+1]);
                }
            }
        }

        uint32_t w = epilogue_word(a);
        g_border[rowbase + (size_t)(y0 + (pv >> 5)) * WW + (x0 + (pv & 31))] = w;
        myor |= w;
    }

    // Publish this 32x32 tile's OR so stage2 can skip before loading anything.
    uint32_t tileor = (uint32_t)__syncthreads_or((int)myor);
    if (tid == 0)
        g_tilemask[b * 256 + blockIdx.y * 16 + blockIdx.x] = tileor;
}

// ---------------------------------------------------------------------------
// Stage 2: depthwise 23x23 conv + spike combination. ONE (tile, group) per
// block. EARLY SKIP: probe <=12 tile-mask words (32x32 each) over the halo;
// if this group's nibble is zero there, exit before loading anything.
// Block (32,4), tile 32x64, 16 output rows/thread, rolling window +
// depth-1 weight prefetch. Results combine via predicated atomicAdd.
// ---------------------------------------------------------------------------
__global__ __launch_bounds__(128)
void stage2_kernel(const float* __restrict__ Wg, float* __restrict__ out)
{
    __shared__ ull sh[86][55];    // decoded (chanA, chanB) pairs (37.8 KB)
    __shared__ ull wsh[529];      // duplicated weights (4.2 KB)

    const int zz  = blockIdx.z;          // 0..31 = b*8 + grp
    const int b   = zz >> 3;
    const int grp = zz & 7;
    const int x0 = blockIdx.x * 32;
    const int y0 = blockIdx.y * 64;
    const int tx = threadIdx.x;   // 0..31
    const int ty = threadIdx.y;   // 0..3
    const int tid = ty * 32 + tx;
    const int yb = ty * 16;
    const int shift = grp * 4;

    // ---- mask probe: OR the <=12 tile-masks (32x32 each) over the halo ----
    {
        const int txl = (x0 >= 11 ? x0 - 11 : 0) >> 5;
        const int txh = ((x0 + 42 < WW ? x0 + 42 : WW - 1)) >> 5;
        const int tyl = (y0 >= 11 ? y0 - 11 : 0) >> 5;
        const int tyh = ((y0 + 74 < HH ? y0 + 74 : HH - 1)) >> 5;
        const int nx = txh - txl + 1;            // <=3
        const int nt = nx * (tyh - tyl + 1);     // <=12
        uint32_t m = 0;
        if (tid < nt) {
            int tyi = tyl + tid / nx;
            int txi = txl + tid % nx;
            m = g_tilemask[b * 256 + tyi * 16 + txi];
        }
        int any = __syncthreads_or((int)((m >> shift) & 0xFu));
        if (!any) return;   // group empty over whole halo -> output untouched
    }

    const uint32_t* __restrict__ bor = g_border + (size_t)b * HH * WW;

    for (int i = tid; i < 529; i += 128) {
        float w = Wg[grp * 2 * 529 + i];
        wsh[i] = pack2(w, w);
    }

    for (int ry = ty; ry < 86; ry += 4) {
        int gy = y0 - 11 + ry;
        for (int rx = tx; rx < 54; rx += 32) {
            int gx = x0 - 11 + rx;
            uint32_t v = 0;
            if (((unsigned)gy < HH) && ((unsigned)gx < WW)) v = bor[gy * WW + gx];
            sh[ry][rx] = pack2((float)((v >> shift) & 3u),
                               (float)((v >> (shift + 2)) & 3u));
        }
    }
    __syncthreads();

    ull a[16];
    #pragma unroll
    for (int o = 0; o < 16; ++o) a[o] = 0ull;

    #pragma unroll 1
    for (int dx = 0; dx < 23; ++dx) {
        const int c = tx + dx;

        ull r[16];
        #pragma unroll
        for (int o = 0; o < 16; ++o) r[o] = sh[yb + o][c];

        ull w0 = wsh[dx];   // weight for dy=0
        #pragma unroll
        for (int dy = 0; dy < 23; ++dy) {
            ull wn = (dy < 22) ? wsh[(dy + 1) * 23 + dx] : 0ull;
            #pragma unroll
            for (int o = 0; o < 16; ++o) a[o] = ffma2(w0, r[o], a[o]);
            if (dy < 22) {
                #pragma unroll
                for (int o = 0; o < 15; ++o) r[o] = r[o + 1];
                r[15] = sh[yb + dy + 16][c];
            }
            w0 = wn;
        }
    }

    #pragma unroll
    for (int o = 0; o < 16; ++o) {
        float2 v = unpack2(a[o]);
        if (v.x >= 1.0f && v.y < 1.0f)
            atomicAdd(&out[((size_t)b * HH + (y0 + yb + o)) * WW + x0 + tx], 1.0f);
    }
}

// ---------------------------------------------------------------------------
extern "C" void kernel_launch(void* const* d_in, const int* in_sizes, int n_in,
                              void* d_out, int out_size)
{
    const float* inp = nullptr;
    const float* Wb  = nullptr;
    const float* Wg  = nullptr;
    for (int i = 0; i < n_in; ++i) {
        if (in_sizes[i] == NB * 2 * HH * WW) inp = (const float*)d_in[i];
        else if (in_sizes[i] == 8 * 121)     Wb  = (const float*)d_in[i];
        else if (in_sizes[i] == 16 * 529)    Wg  = (const float*)d_in[i];
    }

    dim3 grid1(WW / 32, HH / 32, NB);        // 32x32 tiles
    dim3 blk1(32, 4);
    stage1_kernel<<<grid1, blk1>>>(inp, Wb, (float*)d_out);

    dim3 grid2(WW / 32, HH / 64, NB * 8);    // one (32x64 tile, group) per block
    dim3 blk2(32, 4);
    stage2_kernel<<<grid2, blk2>>>(Wg, (float*)d_out);
}